// round 3
// baseline (speedup 1.0000x reference)
#include <cuda_runtime.h>

#define N_NODES 100000
#define N_EDGES 320000
#define N_GRAPHS 4096
#define HID 256
#define NFEAT 28

// ---------------- device scratch (zero-fill bss, no runtime alloc) ----------
__device__ float d_agg28[N_NODES * NFEAT];
__device__ float d_agg[N_NODES * HID];
__device__ float d_x1[N_NODES * HID];
__device__ float d_x2[N_NODES * HID];
__device__ float d_x3[N_NODES * HID];
__device__ float d_x4[N_NODES * HID];
__device__ float d_g[N_GRAPHS * 4 * HID];
__device__ float d_h1[N_GRAPHS * HID];
__device__ float d_h2[N_GRAPHS * HID];
__device__ float d_h3[N_GRAPHS * HID];

// ---------------- utility kernels -------------------------------------------
__global__ void zero_f4(float4* p, int n4) {
    int i = blockIdx.x * blockDim.x + threadIdx.x;
    if (i < n4) p[i] = make_float4(0.f, 0.f, 0.f, 0.f);
}

// scatter-add x[src] (28 feats) into agg28[dst]   (edge_index is int32)
__global__ void scatter28(const float* __restrict__ x,
                          const int* __restrict__ ei,
                          float* __restrict__ agg, int E) {
    int t = blockIdx.x * blockDim.x + threadIdx.x;
    int e = t >> 5;
    int lane = t & 31;
    if (e >= E || lane >= NFEAT) return;
    int s = ei[e];
    int d = ei[E + e];
    atomicAdd(agg + (size_t)d * NFEAT + lane, x[(size_t)s * NFEAT + lane]);
}

// scatter-add x[src] (256 feats) into agg[dst]; 64 threads/edge, float4 gather
__global__ void scatter256(const float* __restrict__ x,
                           const int* __restrict__ ei,
                           float* __restrict__ agg, int E) {
    int t = blockIdx.x * blockDim.x + threadIdx.x;
    int e = t >> 6;
    int c = (t & 63) << 2;
    if (e >= E) return;
    int s = ei[e];
    int d = ei[E + e];
    float4 v = *(const float4*)(x + (size_t)s * HID + c);
    float* p = agg + (size_t)d * HID + c;
    atomicAdd(p + 0, v.x);
    atomicAdd(p + 1, v.y);
    atomicAdd(p + 2, v.z);
    atomicAdd(p + 3, v.w);
}

// layer 1: out = relu(agg28 @ W_rel^T + b + x @ W_root^T)  (K=28, NOUT=256)
__global__ __launch_bounds__(256)
void layer1_kernel(const float* __restrict__ agg28, const float* __restrict__ x,
                   const float* __restrict__ W_rel, const float* __restrict__ b,
                   const float* __restrict__ W_root, float* __restrict__ out, int M) {
    __shared__ float sa[16][NFEAT];
    __shared__ float sx[16][NFEAT];
    int r0 = blockIdx.x * 16;
    for (int i = threadIdx.x; i < 16 * NFEAT; i += 256) {
        int r = i / NFEAT, c = i % NFEAT;
        int row = r0 + r;
        sa[r][c] = (row < M) ? agg28[(size_t)row * NFEAT + c] : 0.f;
        sx[r][c] = (row < M) ? x[(size_t)row * NFEAT + c] : 0.f;
    }
    __syncthreads();
    int o = threadIdx.x;  // output column 0..255
    float wr[NFEAT], wo[NFEAT];
#pragma unroll
    for (int k = 0; k < NFEAT; k++) {
        wr[k] = W_rel[o * NFEAT + k];
        wo[k] = W_root[o * NFEAT + k];
    }
    float bo = b[o];
#pragma unroll 4
    for (int r = 0; r < 16; r++) {
        int row = r0 + r;
        if (row >= M) break;
        float acc = bo;
#pragma unroll
        for (int k = 0; k < NFEAT; k++) acc += sa[r][k] * wr[k] + sx[r][k] * wo[k];
        out[(size_t)row * HID + o] = fmaxf(acc, 0.f);
    }
}

// ------------- dual-segment NT SGEMM -----------------------------------------
// C[M,N] = relu( bias[n] + A0[M,K0] @ B0[N,K0]^T + A1[M,K1] @ B1[N,K1]^T )
// 128x128 tile, BK=8, 8x8 per thread, 256 threads. K0,K1 multiples of 8.
#define BM 128
#define BN 128
#define BK 8

__global__ __launch_bounds__(256, 2)
void gemm_dual_nt(const float* __restrict__ A0, int lda0,
                  const float* __restrict__ B0, int ldb0, int K0,
                  const float* __restrict__ A1, int lda1,
                  const float* __restrict__ B1, int ldb1, int K1,
                  const float* __restrict__ bias, float* __restrict__ C,
                  int M, int N, int ldc, int relu) {
    __shared__ float As[BK][BM];
    __shared__ float Bs[BK][BN];
    int tid = threadIdx.x;
    int bm = blockIdx.y * BM;
    int bn = blockIdx.x * BN;
    int tx = tid & 15;   // 0..15 -> col group
    int ty = tid >> 4;   // 0..15 -> row group
    int aRow = tid >> 1;       // 0..127
    int aCol = (tid & 1) * 4;  // 0 or 4

    float acc[8][8];
#pragma unroll
    for (int i = 0; i < 8; i++)
#pragma unroll
        for (int j = 0; j < 8; j++) acc[i][j] = 0.f;

#pragma unroll 1
    for (int seg = 0; seg < 2; ++seg) {
        const float* A = seg ? A1 : A0;
        const float* B = seg ? B1 : B0;
        int K = seg ? K1 : K0;
        int lda = seg ? lda1 : lda0;
        int ldb = seg ? ldb1 : ldb0;
        if (K <= 0) continue;
#pragma unroll 1
        for (int k0 = 0; k0 < K; k0 += BK) {
            __syncthreads();
            float4 av = make_float4(0.f, 0.f, 0.f, 0.f);
            int row = bm + aRow;
            if (row < M) av = *(const float4*)(A + (size_t)row * lda + k0 + aCol);
            As[aCol + 0][aRow] = av.x;
            As[aCol + 1][aRow] = av.y;
            As[aCol + 2][aRow] = av.z;
            As[aCol + 3][aRow] = av.w;
            float4 bv = make_float4(0.f, 0.f, 0.f, 0.f);
            int col = bn + aRow;
            if (col < N) bv = *(const float4*)(B + (size_t)col * ldb + k0 + aCol);
            Bs[aCol + 0][aRow] = bv.x;
            Bs[aCol + 1][aRow] = bv.y;
            Bs[aCol + 2][aRow] = bv.z;
            Bs[aCol + 3][aRow] = bv.w;
            __syncthreads();
#pragma unroll
            for (int k = 0; k < BK; k++) {
                float4 a0 = *(float4*)&As[k][ty * 8];
                float4 a1 = *(float4*)&As[k][ty * 8 + 4];
                float4 b0 = *(float4*)&Bs[k][tx * 8];
                float4 b1 = *(float4*)&Bs[k][tx * 8 + 4];
                float ra[8] = {a0.x, a0.y, a0.z, a0.w, a1.x, a1.y, a1.z, a1.w};
                float rb[8] = {b0.x, b0.y, b0.z, b0.w, b1.x, b1.y, b1.z, b1.w};
#pragma unroll
                for (int i = 0; i < 8; i++)
#pragma unroll
                    for (int j = 0; j < 8; j++) acc[i][j] += ra[i] * rb[j];
            }
        }
    }

    // epilogue: bias + relu + vectorized store
#pragma unroll
    for (int i = 0; i < 8; i++) {
        int row = bm + ty * 8 + i;
        if (row >= M) continue;
#pragma unroll
        for (int j4 = 0; j4 < 8; j4 += 4) {
            int colb = bn + tx * 8 + j4;
            float4 v;
            v.x = acc[i][j4 + 0] + bias[colb + 0];
            v.y = acc[i][j4 + 1] + bias[colb + 1];
            v.z = acc[i][j4 + 2] + bias[colb + 2];
            v.w = acc[i][j4 + 3] + bias[colb + 3];
            if (relu) {
                v.x = fmaxf(v.x, 0.f);
                v.y = fmaxf(v.y, 0.f);
                v.z = fmaxf(v.z, 0.f);
                v.w = fmaxf(v.w, 0.f);
            }
            *(float4*)(C + (size_t)row * ldc + colb) = v;
        }
    }
}

// ------------- pooling: per-graph mean over concat(x1..x4) -------------------
__device__ __forceinline__ int lower_bound_i(const int* a, int n, int v) {
    int lo = 0, hi = n;
    while (lo < hi) {
        int mid = (lo + hi) >> 1;
        if (a[mid] < v) lo = mid + 1;
        else hi = mid;
    }
    return lo;
}

__global__ __launch_bounds__(256)
void pool_kernel(const float* __restrict__ x1, const float* __restrict__ x2,
                 const float* __restrict__ x3, const float* __restrict__ x4,
                 const int* __restrict__ batch, float* __restrict__ g, int N) {
    int gr = blockIdx.x;
    __shared__ int s_range[2];
    if (threadIdx.x == 0) {
        s_range[0] = lower_bound_i(batch, N, gr);
        s_range[1] = lower_bound_i(batch, N, gr + 1);
    }
    __syncthreads();
    int start = s_range[0], end = s_range[1];
    int tid = threadIdx.x;  // column 0..255
    float a0 = 0.f, a1 = 0.f, a2 = 0.f, a3 = 0.f;
    for (int n = start; n < end; n++) {
        size_t off = (size_t)n * HID + tid;
        a0 += x1[off];
        a1 += x2[off];
        a2 += x3[off];
        a3 += x4[off];
    }
    float inv = 1.f / fmaxf((float)(end - start), 1.f);
    size_t go = (size_t)gr * (4 * HID);
    g[go + 0 * HID + tid] = a0 * inv;
    g[go + 1 * HID + tid] = a1 * inv;
    g[go + 2 * HID + tid] = a2 * inv;
    g[go + 3 * HID + tid] = a3 * inv;
}

// ------------- final fc4: [G,256] @ w[256] + b -> [G] ------------------------
__global__ void fc4_kernel(const float* __restrict__ h, const float* __restrict__ w,
                           const float* __restrict__ b, float* __restrict__ out, int G) {
    int t = blockIdx.x * blockDim.x + threadIdx.x;
    int warp = t >> 5;
    int lane = t & 31;
    if (warp >= G) return;
    float acc = 0.f;
#pragma unroll
    for (int c = lane; c < HID; c += 32) acc += h[(size_t)warp * HID + c] * w[c];
#pragma unroll
    for (int off = 16; off; off >>= 1) acc += __shfl_xor_sync(0xFFFFFFFFu, acc, off);
    if (lane == 0) out[warp] = acc + b[0];
}

// ---------------- host orchestration ----------------------------------------
extern "C" void kernel_launch(void* const* d_in, const int* in_sizes, int n_in,
                              void* d_out, int out_size) {
    const float* x = (const float*)d_in[0];
    const int* ei = (const int*)d_in[1];       // int32 (JAX x64 disabled)
    const int* batch = (const int*)d_in[2];    // int32
    const float* W_rel[4] = {(const float*)d_in[3], (const float*)d_in[6],
                             (const float*)d_in[9], (const float*)d_in[12]};
    const float* b_rel[4] = {(const float*)d_in[4], (const float*)d_in[7],
                             (const float*)d_in[10], (const float*)d_in[13]};
    const float* W_root[4] = {(const float*)d_in[5], (const float*)d_in[8],
                              (const float*)d_in[11], (const float*)d_in[14]};
    const float* fc1_w = (const float*)d_in[15];
    const float* fc1_b = (const float*)d_in[16];
    const float* fc2_w = (const float*)d_in[17];
    const float* fc2_b = (const float*)d_in[18];
    const float* fc3_w = (const float*)d_in[19];
    const float* fc3_b = (const float*)d_in[20];
    const float* fc4_w = (const float*)d_in[21];
    const float* fc4_b = (const float*)d_in[22];
    float* out = (float*)d_out;

    int N = in_sizes[0] / NFEAT;   // 100000
    int E = in_sizes[1] / 2;       // 320000
    int G = out_size;              // 4096

    // Resolve scratch addresses once per process (host-side query, no alloc).
    static float *agg28 = 0, *agg = 0, *x1 = 0, *x2 = 0, *x3 = 0, *x4 = 0,
                 *g = 0, *h1 = 0, *h2 = 0, *h3 = 0;
    if (!agg28) {
        cudaGetSymbolAddress((void**)&agg28, d_agg28);
        cudaGetSymbolAddress((void**)&agg, d_agg);
        cudaGetSymbolAddress((void**)&x1, d_x1);
        cudaGetSymbolAddress((void**)&x2, d_x2);
        cudaGetSymbolAddress((void**)&x3, d_x3);
        cudaGetSymbolAddress((void**)&x4, d_x4);
        cudaGetSymbolAddress((void**)&g, d_g);
        cudaGetSymbolAddress((void**)&h1, d_h1);
        cudaGetSymbolAddress((void**)&h2, d_h2);
        cudaGetSymbolAddress((void**)&h3, d_h3);
    }

    float* xs[4] = {x1, x2, x3, x4};

    // ---- layer 1: scatter in 28-dim space, then tiny-K fused GEMM ----
    {
        int n4 = N * NFEAT / 4;
        zero_f4<<<(n4 + 255) / 256, 256>>>((float4*)agg28, n4);
        int tot = E * 32;
        scatter28<<<(tot + 255) / 256, 256>>>(x, ei, agg28, E);
        layer1_kernel<<<(N + 15) / 16, 256>>>(agg28, x, W_rel[0], b_rel[0], W_root[0], x1, N);
    }

    // ---- layers 2..4 ----
    for (int l = 1; l < 4; l++) {
        const float* xin = xs[l - 1];
        float* xout = xs[l];
        int n4 = N * HID / 4;
        zero_f4<<<(n4 + 255) / 256, 256>>>((float4*)agg, n4);
        int tot = E * 64;
        scatter256<<<(tot + 255) / 256, 256>>>(xin, ei, agg, E);
        dim3 grid(HID / BN, (N + BM - 1) / BM);
        gemm_dual_nt<<<grid, 256>>>(agg, HID, W_rel[l], HID, HID,
                                    xin, HID, W_root[l], HID, HID,
                                    b_rel[l], xout, N, HID, HID, 1);
    }

    // ---- global mean pool ----
    pool_kernel<<<G, 256>>>(x1, x2, x3, x4, batch, g, N);

    // ---- MLP ----
    {
        dim3 grid(HID / BN, (G + BM - 1) / BM);
        gemm_dual_nt<<<grid, 256>>>(g, 4 * HID, fc1_w, 4 * HID, 4 * HID,
                                    (const float*)0, 0, (const float*)0, 0, 0,
                                    fc1_b, h1, G, HID, HID, 1);
        gemm_dual_nt<<<grid, 256>>>(h1, HID, fc2_w, HID, HID,
                                    (const float*)0, 0, (const float*)0, 0, 0,
                                    fc2_b, h2, G, HID, HID, 1);
        gemm_dual_nt<<<grid, 256>>>(h2, HID, fc3_w, HID, HID,
                                    (const float*)0, 0, (const float*)0, 0, 0,
                                    fc3_b, h3, G, HID, HID, 1);
        int tot = G * 32;
        fc4_kernel<<<(tot + 255) / 256, 256>>>(h3, fc4_w, fc4_b, out, G);
    }
}

// round 5
// speedup vs baseline: 1.8876x; 1.8876x over previous
#include <cuda_runtime.h>
#include <cstdint>

#define N_NODES 100000
#define N_EDGES 320000
#define N_GRAPHS 4096
#define HID 256
#define NFEAT 28

// ---------------- device scratch (zero-fill bss, no runtime alloc) ----------
__device__ float d_agg28[N_NODES * NFEAT];
__device__ float d_agg[N_NODES * HID];
__device__ float d_x1[N_NODES * HID];
__device__ float d_x2[N_NODES * HID];
__device__ float d_x3[N_NODES * HID];
__device__ float d_x4[N_NODES * HID];
__device__ float d_g[N_GRAPHS * 4 * HID];
__device__ float d_h1[N_GRAPHS * HID];
__device__ float d_h2[N_GRAPHS * HID];
__device__ float d_h3[N_GRAPHS * HID];

// ---------------- utility kernels -------------------------------------------
__global__ void zero_f4(float4* p, int n4) {
    int i = blockIdx.x * blockDim.x + threadIdx.x;
    if (i < n4) p[i] = make_float4(0.f, 0.f, 0.f, 0.f);
}

// scatter-add x[src] (28 feats) into agg28[dst]   (edge_index is int32)
__global__ void scatter28(const float* __restrict__ x,
                          const int* __restrict__ ei,
                          float* __restrict__ agg, int E) {
    int t = blockIdx.x * blockDim.x + threadIdx.x;
    int e = t >> 5;
    int lane = t & 31;
    if (e >= E || lane >= NFEAT) return;
    int s = ei[e];
    int d = ei[E + e];
    atomicAdd(agg + (size_t)d * NFEAT + lane, x[(size_t)s * NFEAT + lane]);
}

// scatter-add x[src] (256 feats) into agg[dst]; 64 threads/edge, float4 gather
__global__ void scatter256(const float* __restrict__ x,
                           const int* __restrict__ ei,
                           float* __restrict__ agg, int E) {
    int t = blockIdx.x * blockDim.x + threadIdx.x;
    int e = t >> 6;
    int c = (t & 63) << 2;
    if (e >= E) return;
    int s = ei[e];
    int d = ei[E + e];
    float4 v = *(const float4*)(x + (size_t)s * HID + c);
    float* p = agg + (size_t)d * HID + c;
    atomicAdd(p + 0, v.x);
    atomicAdd(p + 1, v.y);
    atomicAdd(p + 2, v.z);
    atomicAdd(p + 3, v.w);
}

// layer 1: out = relu(agg28 @ W_rel^T + b + x @ W_root^T)  (K=28, NOUT=256)
__global__ __launch_bounds__(256)
void layer1_kernel(const float* __restrict__ agg28, const float* __restrict__ x,
                   const float* __restrict__ W_rel, const float* __restrict__ b,
                   const float* __restrict__ W_root, float* __restrict__ out, int M) {
    __shared__ float sa[16][NFEAT];
    __shared__ float sx[16][NFEAT];
    int r0 = blockIdx.x * 16;
    for (int i = threadIdx.x; i < 16 * NFEAT; i += 256) {
        int r = i / NFEAT, c = i % NFEAT;
        int row = r0 + r;
        sa[r][c] = (row < M) ? agg28[(size_t)row * NFEAT + c] : 0.f;
        sx[r][c] = (row < M) ? x[(size_t)row * NFEAT + c] : 0.f;
    }
    __syncthreads();
    int o = threadIdx.x;  // output column 0..255
    float wr[NFEAT], wo[NFEAT];
#pragma unroll
    for (int k = 0; k < NFEAT; k++) {
        wr[k] = W_rel[o * NFEAT + k];
        wo[k] = W_root[o * NFEAT + k];
    }
    float bo = b[o];
#pragma unroll 4
    for (int r = 0; r < 16; r++) {
        int row = r0 + r;
        if (row >= M) break;
        float acc = bo;
#pragma unroll
        for (int k = 0; k < NFEAT; k++) acc += sa[r][k] * wr[k] + sx[r][k] * wo[k];
        out[(size_t)row * HID + o] = fmaxf(acc, 0.f);
    }
}

// =================== tf32 tensor-core dual-segment NT GEMM ===================
// C[M,256] = relu?( bias + A0[M,K0] @ B0[256,K0]^T + A1[M,K1] @ B1[256,K1]^T )
// Tiles: 128x128 CTA, BK=16, 8 warps (4 in M x 2 in N), warp tile 32x64.
// mma.sync.aligned.m16n8k8 tf32. Inputs rounded with cvt.rna at smem store.
// Requires N == 256, K0/K1 multiples of 16.

#define GBM 128
#define GBN 128
#define GBK 16
#define SSTR 20  // smem row stride in floats (conflict-free, 16B-aligned rows)

__device__ __forceinline__ float to_tf32(float x) {
    uint32_t u;
    asm("cvt.rna.tf32.f32 %0, %1;" : "=r"(u) : "f"(x));
    return __uint_as_float(u);
}

__device__ __forceinline__ void cvt4(float4& v) {
    v.x = to_tf32(v.x); v.y = to_tf32(v.y); v.z = to_tf32(v.z); v.w = to_tf32(v.w);
}

__device__ __forceinline__ void mma_tf32(float* c, const uint32_t* a, const uint32_t* b) {
    asm volatile(
        "mma.sync.aligned.m16n8k8.row.col.f32.tf32.tf32.f32 "
        "{%0,%1,%2,%3}, {%4,%5,%6,%7}, {%8,%9}, {%0,%1,%2,%3};"
        : "+f"(c[0]), "+f"(c[1]), "+f"(c[2]), "+f"(c[3])
        : "r"(a[0]), "r"(a[1]), "r"(a[2]), "r"(a[3]), "r"(b[0]), "r"(b[1]));
}

__global__ __launch_bounds__(256, 2)
void gemm_tf32_dual(const float* __restrict__ A0, int lda0,
                    const float* __restrict__ B0, int ldb0, int K0,
                    const float* __restrict__ A1, int lda1,
                    const float* __restrict__ B1, int ldb1, int K1,
                    const float* __restrict__ bias, float* __restrict__ C,
                    int M, int ldc, int relu) {
    __shared__ float As[2][GBM * SSTR];
    __shared__ float Bs[2][GBN * SSTR];

    int tid = threadIdx.x;
    int lane = tid & 31;
    int wid = tid >> 5;
    int wm = wid & 3;   // 0..3 -> 32-row slice
    int wn = wid >> 2;  // 0..1 -> 64-col slice
    int bm = blockIdx.y * GBM;
    int bn = blockIdx.x * GBN;

    float acc[2][8][4];
#pragma unroll
    for (int mt = 0; mt < 2; mt++)
#pragma unroll
        for (int nt = 0; nt < 8; nt++)
#pragma unroll
            for (int i = 0; i < 4; i++) acc[mt][nt][i] = 0.f;

    int nk0 = K0 / GBK;
    int nk = nk0 + K1 / GBK;

    int lr = tid >> 2;            // 0..63
    int lc = (tid & 3) << 2;      // 0,4,8,12
    float4 a_st[2], b_st[2];

    // ---- stage 0 ----
    {
        const float* A = (0 < nk0) ? A0 : A1;
        const float* B = (0 < nk0) ? B0 : B1;
        int lda = (0 < nk0) ? lda0 : lda1;
        int ldb = (0 < nk0) ? ldb0 : ldb1;
#pragma unroll
        for (int j = 0; j < 2; j++) {
            int rr = lr + j * 64;
            int row = bm + rr;
            a_st[j] = (row < M) ? *(const float4*)(A + (size_t)row * lda + lc)
                                : make_float4(0.f, 0.f, 0.f, 0.f);
            b_st[j] = *(const float4*)(B + (size_t)(bn + rr) * ldb + lc);
        }
#pragma unroll
        for (int j = 0; j < 2; j++) {
            int rr = lr + j * 64;
            float4 a = a_st[j], b = b_st[j];
            cvt4(a); cvt4(b);
            *(float4*)&As[0][rr * SSTR + lc] = a;
            *(float4*)&Bs[0][rr * SSTR + lc] = b;
        }
    }
    __syncthreads();

    int buf = 0;
    int grp = lane >> 2;  // 0..7
    int qid = lane & 3;   // 0..3

    for (int it = 0; it < nk; ++it) {
        bool more = (it + 1) < nk;
        if (more) {
            int nx = it + 1;
            const float* A; const float* B; int lda, ldb, ko;
            if (nx < nk0) { A = A0; B = B0; lda = lda0; ldb = ldb0; ko = nx * GBK; }
            else          { A = A1; B = B1; lda = lda1; ldb = ldb1; ko = (nx - nk0) * GBK; }
#pragma unroll
            for (int j = 0; j < 2; j++) {
                int rr = lr + j * 64;
                int row = bm + rr;
                a_st[j] = (row < M) ? *(const float4*)(A + (size_t)row * lda + ko + lc)
                                    : make_float4(0.f, 0.f, 0.f, 0.f);
                b_st[j] = *(const float4*)(B + (size_t)(bn + rr) * ldb + ko + lc);
            }
        }

        // ---- compute from As[buf]/Bs[buf] ----
#pragma unroll
        for (int kk = 0; kk < GBK; kk += 8) {
            uint32_t af[2][4];
            uint32_t bfr[8][2];
#pragma unroll
            for (int mt = 0; mt < 2; mt++) {
                int r0 = wm * 32 + mt * 16 + grp;
                const float* base = &As[buf][0];
                af[mt][0] = __float_as_uint(base[(r0    ) * SSTR + kk + qid]);
                af[mt][1] = __float_as_uint(base[(r0 + 8) * SSTR + kk + qid]);
                af[mt][2] = __float_as_uint(base[(r0    ) * SSTR + kk + qid + 4]);
                af[mt][3] = __float_as_uint(base[(r0 + 8) * SSTR + kk + qid + 4]);
            }
#pragma unroll
            for (int nt = 0; nt < 8; nt++) {
                int n0 = wn * 64 + nt * 8 + grp;
                bfr[nt][0] = __float_as_uint(Bs[buf][n0 * SSTR + kk + qid]);
                bfr[nt][1] = __float_as_uint(Bs[buf][n0 * SSTR + kk + qid + 4]);
            }
#pragma unroll
            for (int mt = 0; mt < 2; mt++)
#pragma unroll
                for (int nt = 0; nt < 8; nt++) mma_tf32(acc[mt][nt], af[mt], bfr[nt]);
        }

        if (more) {
#pragma unroll
            for (int j = 0; j < 2; j++) {
                int rr = lr + j * 64;
                float4 a = a_st[j], b = b_st[j];
                cvt4(a); cvt4(b);
                *(float4*)&As[buf ^ 1][rr * SSTR + lc] = a;
                *(float4*)&Bs[buf ^ 1][rr * SSTR + lc] = b;
            }
        }
        __syncthreads();
        buf ^= 1;
    }

    // ---- epilogue: bias + optional relu ----
#pragma unroll
    for (int mt = 0; mt < 2; mt++) {
#pragma unroll
        for (int nt = 0; nt < 8; nt++) {
            int row = bm + wm * 32 + mt * 16 + grp;
            int col = bn + wn * 64 + nt * 8 + 2 * qid;
            float b0 = bias[col], b1 = bias[col + 1];
            float2 v0, v1;
            v0.x = acc[mt][nt][0] + b0; v0.y = acc[mt][nt][1] + b1;
            v1.x = acc[mt][nt][2] + b0; v1.y = acc[mt][nt][3] + b1;
            if (relu) {
                v0.x = fmaxf(v0.x, 0.f); v0.y = fmaxf(v0.y, 0.f);
                v1.x = fmaxf(v1.x, 0.f); v1.y = fmaxf(v1.y, 0.f);
            }
            if (row < M)     *(float2*)(C + (size_t)row * ldc + col) = v0;
            if (row + 8 < M) *(float2*)(C + (size_t)(row + 8) * ldc + col) = v1;
        }
    }
}

// ------------- pooling: per-graph mean over concat(x1..x4) -------------------
__device__ __forceinline__ int lower_bound_i(const int* a, int n, int v) {
    int lo = 0, hi = n;
    while (lo < hi) {
        int mid = (lo + hi) >> 1;
        if (a[mid] < v) lo = mid + 1;
        else hi = mid;
    }
    return lo;
}

__global__ __launch_bounds__(256)
void pool_kernel(const float* __restrict__ x1, const float* __restrict__ x2,
                 const float* __restrict__ x3, const float* __restrict__ x4,
                 const int* __restrict__ batch, float* __restrict__ g, int N) {
    int gr = blockIdx.x;
    __shared__ int s_range[2];
    if (threadIdx.x == 0) {
        s_range[0] = lower_bound_i(batch, N, gr);
        s_range[1] = lower_bound_i(batch, N, gr + 1);
    }
    __syncthreads();
    int start = s_range[0], end = s_range[1];
    int tid = threadIdx.x;  // column 0..255
    float a0 = 0.f, a1 = 0.f, a2 = 0.f, a3 = 0.f;
    for (int n = start; n < end; n++) {
        size_t off = (size_t)n * HID + tid;
        a0 += x1[off];
        a1 += x2[off];
        a2 += x3[off];
        a3 += x4[off];
    }
    float inv = 1.f / fmaxf((float)(end - start), 1.f);
    size_t go = (size_t)gr * (4 * HID);
    g[go + 0 * HID + tid] = a0 * inv;
    g[go + 1 * HID + tid] = a1 * inv;
    g[go + 2 * HID + tid] = a2 * inv;
    g[go + 3 * HID + tid] = a3 * inv;
}

// ------------- final fc4: [G,256] @ w[256] + b -> [G] ------------------------
__global__ void fc4_kernel(const float* __restrict__ h, const float* __restrict__ w,
                           const float* __restrict__ b, float* __restrict__ out, int G) {
    int t = blockIdx.x * blockDim.x + threadIdx.x;
    int warp = t >> 5;
    int lane = t & 31;
    if (warp >= G) return;
    float acc = 0.f;
#pragma unroll
    for (int c = lane; c < HID; c += 32) acc += h[(size_t)warp * HID + c] * w[c];
#pragma unroll
    for (int off = 16; off; off >>= 1) acc += __shfl_xor_sync(0xFFFFFFFFu, acc, off);
    if (lane == 0) out[warp] = acc + b[0];
}

// ---------------- host orchestration ----------------------------------------
extern "C" void kernel_launch(void* const* d_in, const int* in_sizes, int n_in,
                              void* d_out, int out_size) {
    const float* x = (const float*)d_in[0];
    const int* ei = (const int*)d_in[1];       // int32 (JAX x64 disabled)
    const int* batch = (const int*)d_in[2];    // int32
    const float* W_rel[4] = {(const float*)d_in[3], (const float*)d_in[6],
                             (const float*)d_in[9], (const float*)d_in[12]};
    const float* b_rel[4] = {(const float*)d_in[4], (const float*)d_in[7],
                             (const float*)d_in[10], (const float*)d_in[13]};
    const float* W_root[4] = {(const float*)d_in[5], (const float*)d_in[8],
                              (const float*)d_in[11], (const float*)d_in[14]};
    const float* fc1_w = (const float*)d_in[15];
    const float* fc1_b = (const float*)d_in[16];
    const float* fc2_w = (const float*)d_in[17];
    const float* fc2_b = (const float*)d_in[18];
    const float* fc3_w = (const float*)d_in[19];
    const float* fc3_b = (const float*)d_in[20];
    const float* fc4_w = (const float*)d_in[21];
    const float* fc4_b = (const float*)d_in[22];
    float* out = (float*)d_out;

    int N = in_sizes[0] / NFEAT;   // 100000
    int E = in_sizes[1] / 2;       // 320000
    int G = out_size;              // 4096

    static float *agg28 = 0, *agg = 0, *x1 = 0, *x2 = 0, *x3 = 0, *x4 = 0,
                 *g = 0, *h1 = 0, *h2 = 0, *h3 = 0;
    if (!agg28) {
        cudaGetSymbolAddress((void**)&agg28, d_agg28);
        cudaGetSymbolAddress((void**)&agg, d_agg);
        cudaGetSymbolAddress((void**)&x1, d_x1);
        cudaGetSymbolAddress((void**)&x2, d_x2);
        cudaGetSymbolAddress((void**)&x3, d_x3);
        cudaGetSymbolAddress((void**)&x4, d_x4);
        cudaGetSymbolAddress((void**)&g, d_g);
        cudaGetSymbolAddress((void**)&h1, d_h1);
        cudaGetSymbolAddress((void**)&h2, d_h2);
        cudaGetSymbolAddress((void**)&h3, d_h3);
    }

    float* xs[4] = {x1, x2, x3, x4};

    // ---- layer 1: scatter in 28-dim space, then tiny-K fused GEMM (fp32) ----
    {
        int n4 = N * NFEAT / 4;
        zero_f4<<<(n4 + 255) / 256, 256>>>((float4*)agg28, n4);
        int tot = E * 32;
        scatter28<<<(tot + 255) / 256, 256>>>(x, ei, agg28, E);
        layer1_kernel<<<(N + 15) / 16, 256>>>(agg28, x, W_rel[0], b_rel[0], W_root[0], x1, N);
    }

    // ---- layers 2..4 : scatter + tf32 dual GEMM ----
    for (int l = 1; l < 4; l++) {
        const float* xin = xs[l - 1];
        float* xout = xs[l];
        int n4 = N * HID / 4;
        zero_f4<<<(n4 + 255) / 256, 256>>>((float4*)agg, n4);
        int tot = E * 64;
        scatter256<<<(tot + 255) / 256, 256>>>(xin, ei, agg, E);
        dim3 grid(HID / GBN, (N + GBM - 1) / GBM);
        gemm_tf32_dual<<<grid, 256>>>(agg, HID, W_rel[l], HID, HID,
                                      xin, HID, W_root[l], HID, HID,
                                      b_rel[l], xout, N, HID, 1);
    }

    // ---- global mean pool ----
    pool_kernel<<<G, 256>>>(x1, x2, x3, x4, batch, g, N);

    // ---- MLP (tf32 for fc1..fc3, warp-reduce for fc4) ----
    {
        dim3 grid(HID / GBN, (G + GBM - 1) / GBM);
        gemm_tf32_dual<<<grid, 256>>>(g, 4 * HID, fc1_w, 4 * HID, 4 * HID,
                                      (const float*)0, 0, (const float*)0, 0, 0,
                                      fc1_b, h1, G, HID, 1);
        gemm_tf32_dual<<<grid, 256>>>(h1, HID, fc2_w, HID, HID,
                                      (const float*)0, 0, (const float*)0, 0, 0,
                                      fc2_b, h2, G, HID, 1);
        gemm_tf32_dual<<<grid, 256>>>(h2, HID, fc3_w, HID, HID,
                                      (const float*)0, 0, (const float*)0, 0, 0,
                                      fc3_b, h3, G, HID, 1);
        int tot = G * 32;
        fc4_kernel<<<(tot + 255) / 256, 256>>>(h3, fc4_w, fc4_b, out, G);
    }
}

// round 6
// speedup vs baseline: 2.3565x; 1.2484x over previous
#include <cuda_runtime.h>
#include <cstdint>

#define N_NODES 100000
#define N_EDGES 320000
#define N_GRAPHS 4096
#define HID 256
#define NFEAT 28

// ---------------- device scratch (zero-fill bss, no runtime alloc) ----------
__device__ float d_agg28[N_NODES * NFEAT];
__device__ float d_agg[N_NODES * HID];
__device__ float d_x1[N_NODES * HID];
__device__ float d_x2[N_NODES * HID];
__device__ float d_x3[N_NODES * HID];
__device__ float d_x4[N_NODES * HID];
__device__ float d_g[N_GRAPHS * 4 * HID];
__device__ float d_h1[N_GRAPHS * HID];
__device__ float d_h2[N_GRAPHS * HID];
__device__ float d_h3[N_GRAPHS * HID];

// ---------------- utility kernels -------------------------------------------
__global__ void zero_f4(float4* p, int n4) {
    int i = blockIdx.x * blockDim.x + threadIdx.x;
    if (i < n4) p[i] = make_float4(0.f, 0.f, 0.f, 0.f);
}

__device__ __forceinline__ void red_add_v4(float* p, float4 v) {
    asm volatile("red.global.add.v4.f32 [%0], {%1,%2,%3,%4};"
                 :: "l"(p), "f"(v.x), "f"(v.y), "f"(v.z), "f"(v.w)
                 : "memory");
}

// scatter-add x[src] (28 feats = 7 float4) into agg28[dst]; 8 threads/edge
__global__ void scatter28(const float* __restrict__ x,
                          const int* __restrict__ ei,
                          float* __restrict__ agg, int E) {
    int t = blockIdx.x * blockDim.x + threadIdx.x;
    int e = t >> 3;
    int c = t & 7;
    if (e >= E || c >= 7) return;
    int s = ei[e];
    int d = ei[E + e];
    float4 v = *(const float4*)(x + (size_t)s * NFEAT + c * 4);
    red_add_v4(agg + (size_t)d * NFEAT + c * 4, v);
}

// scatter-add x[src] (256 feats) into agg[dst]; 64 threads/edge, red.v4
__global__ void scatter256(const float* __restrict__ x,
                           const int* __restrict__ ei,
                           float* __restrict__ agg, int E) {
    int t = blockIdx.x * blockDim.x + threadIdx.x;
    int e = t >> 6;
    int c = (t & 63) << 2;
    if (e >= E) return;
    int s = ei[e];
    int d = ei[E + e];
    float4 v = *(const float4*)(x + (size_t)s * HID + c);
    red_add_v4(agg + (size_t)d * HID + c, v);
}

// layer 1: out = relu(agg28 @ W_rel^T + b + x @ W_root^T)  (K=28, NOUT=256)
__global__ __launch_bounds__(256)
void layer1_kernel(const float* __restrict__ agg28, const float* __restrict__ x,
                   const float* __restrict__ W_rel, const float* __restrict__ b,
                   const float* __restrict__ W_root, float* __restrict__ out, int M) {
    __shared__ float sa[16][NFEAT];
    __shared__ float sx[16][NFEAT];
    int r0 = blockIdx.x * 16;
    for (int i = threadIdx.x; i < 16 * NFEAT; i += 256) {
        int r = i / NFEAT, c = i % NFEAT;
        int row = r0 + r;
        sa[r][c] = (row < M) ? agg28[(size_t)row * NFEAT + c] : 0.f;
        sx[r][c] = (row < M) ? x[(size_t)row * NFEAT + c] : 0.f;
    }
    __syncthreads();
    int o = threadIdx.x;  // output column 0..255
    float wr[NFEAT], wo[NFEAT];
#pragma unroll
    for (int k = 0; k < NFEAT; k++) {
        wr[k] = W_rel[o * NFEAT + k];
        wo[k] = W_root[o * NFEAT + k];
    }
    float bo = b[o];
#pragma unroll 4
    for (int r = 0; r < 16; r++) {
        int row = r0 + r;
        if (row >= M) break;
        float acc = bo;
#pragma unroll
        for (int k = 0; k < NFEAT; k++) acc += sa[r][k] * wr[k] + sx[r][k] * wo[k];
        out[(size_t)row * HID + o] = fmaxf(acc, 0.f);
    }
}

// =================== tf32 tensor-core dual-segment NT GEMM ===================
// C[M,256] = relu?( bias + A0[M,K0] @ B0[256,K0]^T + A1[M,K1] @ B1[256,K1]^T )
// Tiles: 128x128 CTA, BK=16, 8 warps (4 in M x 2 in N), warp tile 32x64.

#define GBM 128
#define GBN 128
#define GBK 16
#define SSTR 20  // smem row stride in floats (conflict-free, 16B-aligned rows)

__device__ __forceinline__ float to_tf32(float x) {
    uint32_t u;
    asm("cvt.rna.tf32.f32 %0, %1;" : "=r"(u) : "f"(x));
    return __uint_as_float(u);
}

__device__ __forceinline__ void cvt4(float4& v) {
    v.x = to_tf32(v.x); v.y = to_tf32(v.y); v.z = to_tf32(v.z); v.w = to_tf32(v.w);
}

__device__ __forceinline__ void mma_tf32(float* c, const uint32_t* a, const uint32_t* b) {
    asm volatile(
        "mma.sync.aligned.m16n8k8.row.col.f32.tf32.tf32.f32 "
        "{%0,%1,%2,%3}, {%4,%5,%6,%7}, {%8,%9}, {%0,%1,%2,%3};"
        : "+f"(c[0]), "+f"(c[1]), "+f"(c[2]), "+f"(c[3])
        : "r"(a[0]), "r"(a[1]), "r"(a[2]), "r"(a[3]), "r"(b[0]), "r"(b[1]));
}

__global__ __launch_bounds__(256, 2)
void gemm_tf32_dual(const float* __restrict__ A0, int lda0,
                    const float* __restrict__ B0, int ldb0, int K0,
                    const float* __restrict__ A1, int lda1,
                    const float* __restrict__ B1, int ldb1, int K1,
                    const float* __restrict__ bias, float* __restrict__ C,
                    int M, int ldc, int relu) {
    __shared__ float As[2][GBM * SSTR];
    __shared__ float Bs[2][GBN * SSTR];

    int tid = threadIdx.x;
    int lane = tid & 31;
    int wid = tid >> 5;
    int wm = wid & 3;   // 0..3 -> 32-row slice
    int wn = wid >> 2;  // 0..1 -> 64-col slice
    int bm = blockIdx.y * GBM;
    int bn = blockIdx.x * GBN;

    float acc[2][8][4];
#pragma unroll
    for (int mt = 0; mt < 2; mt++)
#pragma unroll
        for (int nt = 0; nt < 8; nt++)
#pragma unroll
            for (int i = 0; i < 4; i++) acc[mt][nt][i] = 0.f;

    int nk0 = K0 / GBK;
    int nk = nk0 + K1 / GBK;

    int lr = tid >> 2;            // 0..63
    int lc = (tid & 3) << 2;      // 0,4,8,12
    float4 a_st[2], b_st[2];

    // ---- stage 0 ----
    {
        const float* A = (0 < nk0) ? A0 : A1;
        const float* B = (0 < nk0) ? B0 : B1;
        int lda = (0 < nk0) ? lda0 : lda1;
        int ldb = (0 < nk0) ? ldb0 : ldb1;
#pragma unroll
        for (int j = 0; j < 2; j++) {
            int rr = lr + j * 64;
            int row = bm + rr;
            a_st[j] = (row < M) ? *(const float4*)(A + (size_t)row * lda + lc)
                                : make_float4(0.f, 0.f, 0.f, 0.f);
            b_st[j] = *(const float4*)(B + (size_t)(bn + rr) * ldb + lc);
        }
#pragma unroll
        for (int j = 0; j < 2; j++) {
            int rr = lr + j * 64;
            float4 a = a_st[j], b = b_st[j];
            cvt4(a); cvt4(b);
            *(float4*)&As[0][rr * SSTR + lc] = a;
            *(float4*)&Bs[0][rr * SSTR + lc] = b;
        }
    }
    __syncthreads();

    int buf = 0;
    int grp = lane >> 2;  // 0..7
    int qid = lane & 3;   // 0..3

    for (int it = 0; it < nk; ++it) {
        bool more = (it + 1) < nk;
        if (more) {
            int nx = it + 1;
            const float* A; const float* B; int lda, ldb, ko;
            if (nx < nk0) { A = A0; B = B0; lda = lda0; ldb = ldb0; ko = nx * GBK; }
            else          { A = A1; B = B1; lda = lda1; ldb = ldb1; ko = (nx - nk0) * GBK; }
#pragma unroll
            for (int j = 0; j < 2; j++) {
                int rr = lr + j * 64;
                int row = bm + rr;
                a_st[j] = (row < M) ? *(const float4*)(A + (size_t)row * lda + ko + lc)
                                    : make_float4(0.f, 0.f, 0.f, 0.f);
                b_st[j] = *(const float4*)(B + (size_t)(bn + rr) * ldb + ko + lc);
            }
        }

        // ---- compute from As[buf]/Bs[buf] ----
#pragma unroll
        for (int kk = 0; kk < GBK; kk += 8) {
            uint32_t af[2][4];
            uint32_t bfr[8][2];
#pragma unroll
            for (int mt = 0; mt < 2; mt++) {
                int r0 = wm * 32 + mt * 16 + grp;
                const float* base = &As[buf][0];
                af[mt][0] = __float_as_uint(base[(r0    ) * SSTR + kk + qid]);
                af[mt][1] = __float_as_uint(base[(r0 + 8) * SSTR + kk + qid]);
                af[mt][2] = __float_as_uint(base[(r0    ) * SSTR + kk + qid + 4]);
                af[mt][3] = __float_as_uint(base[(r0 + 8) * SSTR + kk + qid + 4]);
            }
#pragma unroll
            for (int nt = 0; nt < 8; nt++) {
                int n0 = wn * 64 + nt * 8 + grp;
                bfr[nt][0] = __float_as_uint(Bs[buf][n0 * SSTR + kk + qid]);
                bfr[nt][1] = __float_as_uint(Bs[buf][n0 * SSTR + kk + qid + 4]);
            }
#pragma unroll
            for (int mt = 0; mt < 2; mt++)
#pragma unroll
                for (int nt = 0; nt < 8; nt++) mma_tf32(acc[mt][nt], af[mt], bfr[nt]);
        }

        if (more) {
#pragma unroll
            for (int j = 0; j < 2; j++) {
                int rr = lr + j * 64;
                float4 a = a_st[j], b = b_st[j];
                cvt4(a); cvt4(b);
                *(float4*)&As[buf ^ 1][rr * SSTR + lc] = a;
                *(float4*)&Bs[buf ^ 1][rr * SSTR + lc] = b;
            }
        }
        __syncthreads();
        buf ^= 1;
    }

    // ---- epilogue: bias + optional relu ----
#pragma unroll
    for (int mt = 0; mt < 2; mt++) {
#pragma unroll
        for (int nt = 0; nt < 8; nt++) {
            int row = bm + wm * 32 + mt * 16 + grp;
            int col = bn + wn * 64 + nt * 8 + 2 * qid;
            float b0 = bias[col], b1 = bias[col + 1];
            float2 v0, v1;
            v0.x = acc[mt][nt][0] + b0; v0.y = acc[mt][nt][1] + b1;
            v1.x = acc[mt][nt][2] + b0; v1.y = acc[mt][nt][3] + b1;
            if (relu) {
                v0.x = fmaxf(v0.x, 0.f); v0.y = fmaxf(v0.y, 0.f);
                v1.x = fmaxf(v1.x, 0.f); v1.y = fmaxf(v1.y, 0.f);
            }
            if (row < M)     *(float2*)(C + (size_t)row * ldc + col) = v0;
            if (row + 8 < M) *(float2*)(C + (size_t)(row + 8) * ldc + col) = v1;
        }
    }
}

// ------------- pooling: per-graph mean over concat(x1..x4) -------------------
__device__ __forceinline__ int lower_bound_i(const int* a, int n, int v) {
    int lo = 0, hi = n;
    while (lo < hi) {
        int mid = (lo + hi) >> 1;
        if (a[mid] < v) lo = mid + 1;
        else hi = mid;
    }
    return lo;
}

__global__ __launch_bounds__(256)
void pool_kernel(const float* __restrict__ x1, const float* __restrict__ x2,
                 const float* __restrict__ x3, const float* __restrict__ x4,
                 const int* __restrict__ batch, float* __restrict__ g, int N) {
    int gr = blockIdx.x;
    __shared__ int s_range[2];
    if (threadIdx.x == 0) {
        s_range[0] = lower_bound_i(batch, N, gr);
        s_range[1] = lower_bound_i(batch, N, gr + 1);
    }
    __syncthreads();
    int start = s_range[0], end = s_range[1];
    int tid = threadIdx.x;  // column 0..255
    float a0 = 0.f, a1 = 0.f, a2 = 0.f, a3 = 0.f;
    for (int n = start; n < end; n++) {
        size_t off = (size_t)n * HID + tid;
        a0 += x1[off];
        a1 += x2[off];
        a2 += x3[off];
        a3 += x4[off];
    }
    float inv = 1.f / fmaxf((float)(end - start), 1.f);
    size_t go = (size_t)gr * (4 * HID);
    g[go + 0 * HID + tid] = a0 * inv;
    g[go + 1 * HID + tid] = a1 * inv;
    g[go + 2 * HID + tid] = a2 * inv;
    g[go + 3 * HID + tid] = a3 * inv;
}

// ------------- final fc4: [G,256] @ w[256] + b -> [G] ------------------------
__global__ void fc4_kernel(const float* __restrict__ h, const float* __restrict__ w,
                           const float* __restrict__ b, float* __restrict__ out, int G) {
    int t = blockIdx.x * blockDim.x + threadIdx.x;
    int warp = t >> 5;
    int lane = t & 31;
    if (warp >= G) return;
    float acc = 0.f;
#pragma unroll
    for (int c = lane; c < HID; c += 32) acc += h[(size_t)warp * HID + c] * w[c];
#pragma unroll
    for (int off = 16; off; off >>= 1) acc += __shfl_xor_sync(0xFFFFFFFFu, acc, off);
    if (lane == 0) out[warp] = acc + b[0];
}

// ---------------- host orchestration ----------------------------------------
extern "C" void kernel_launch(void* const* d_in, const int* in_sizes, int n_in,
                              void* d_out, int out_size) {
    const float* x = (const float*)d_in[0];
    const int* ei = (const int*)d_in[1];       // int32 (JAX x64 disabled)
    const int* batch = (const int*)d_in[2];    // int32
    const float* W_rel[4] = {(const float*)d_in[3], (const float*)d_in[6],
                             (const float*)d_in[9], (const float*)d_in[12]};
    const float* b_rel[4] = {(const float*)d_in[4], (const float*)d_in[7],
                             (const float*)d_in[10], (const float*)d_in[13]};
    const float* W_root[4] = {(const float*)d_in[5], (const float*)d_in[8],
                              (const float*)d_in[11], (const float*)d_in[14]};
    const float* fc1_w = (const float*)d_in[15];
    const float* fc1_b = (const float*)d_in[16];
    const float* fc2_w = (const float*)d_in[17];
    const float* fc2_b = (const float*)d_in[18];
    const float* fc3_w = (const float*)d_in[19];
    const float* fc3_b = (const float*)d_in[20];
    const float* fc4_w = (const float*)d_in[21];
    const float* fc4_b = (const float*)d_in[22];
    float* out = (float*)d_out;

    int N = in_sizes[0] / NFEAT;   // 100000
    int E = in_sizes[1] / 2;       // 320000
    int G = out_size;              // 4096

    static float *agg28 = 0, *agg = 0, *x1 = 0, *x2 = 0, *x3 = 0, *x4 = 0,
                 *g = 0, *h1 = 0, *h2 = 0, *h3 = 0;
    if (!agg28) {
        cudaGetSymbolAddress((void**)&agg28, d_agg28);
        cudaGetSymbolAddress((void**)&agg, d_agg);
        cudaGetSymbolAddress((void**)&x1, d_x1);
        cudaGetSymbolAddress((void**)&x2, d_x2);
        cudaGetSymbolAddress((void**)&x3, d_x3);
        cudaGetSymbolAddress((void**)&x4, d_x4);
        cudaGetSymbolAddress((void**)&g, d_g);
        cudaGetSymbolAddress((void**)&h1, d_h1);
        cudaGetSymbolAddress((void**)&h2, d_h2);
        cudaGetSymbolAddress((void**)&h3, d_h3);
    }

    float* xs[4] = {x1, x2, x3, x4};

    // ---- layer 1: scatter in 28-dim space, then tiny-K fused GEMM (fp32) ----
    {
        int n4 = N * NFEAT / 4;
        zero_f4<<<(n4 + 255) / 256, 256>>>((float4*)agg28, n4);
        int tot = E * 8;
        scatter28<<<(tot + 255) / 256, 256>>>(x, ei, agg28, E);
        layer1_kernel<<<(N + 15) / 16, 256>>>(agg28, x, W_rel[0], b_rel[0], W_root[0], x1, N);
    }

    // ---- layers 2..4 : scatter (red.v4) + tf32 dual GEMM ----
    for (int l = 1; l < 4; l++) {
        const float* xin = xs[l - 1];
        float* xout = xs[l];
        int n4 = N * HID / 4;
        zero_f4<<<(n4 + 255) / 256, 256>>>((float4*)agg, n4);
        int tot = E * 64;
        scatter256<<<(tot + 255) / 256, 256>>>(xin, ei, agg, E);
        dim3 grid(HID / GBN, (N + GBM - 1) / GBM);
        gemm_tf32_dual<<<grid, 256>>>(agg, HID, W_rel[l], HID, HID,
                                      xin, HID, W_root[l], HID, HID,
                                      b_rel[l], xout, N, HID, 1);
    }

    // ---- global mean pool ----
    pool_kernel<<<G, 256>>>(x1, x2, x3, x4, batch, g, N);

    // ---- MLP (tf32 for fc1..fc3, warp-reduce for fc4) ----
    {
        dim3 grid(HID / GBN, (G + GBM - 1) / GBM);
        gemm_tf32_dual<<<grid, 256>>>(g, 4 * HID, fc1_w, 4 * HID, 4 * HID,
                                      (const float*)0, 0, (const float*)0, 0, 0,
                                      fc1_b, h1, G, HID, 1);
        gemm_tf32_dual<<<grid, 256>>>(h1, HID, fc2_w, HID, HID,
                                      (const float*)0, 0, (const float*)0, 0, 0,
                                      fc2_b, h2, G, HID, 1);
        gemm_tf32_dual<<<grid, 256>>>(h2, HID, fc3_w, HID, HID,
                                      (const float*)0, 0, (const float*)0, 0, 0,
                                      fc3_b, h3, G, HID, 1);
        int tot = G * 32;
        fc4_kernel<<<(tot + 255) / 256, 256>>>(h3, fc4_w, fc4_b, out, G);
    }
}

// round 7
// speedup vs baseline: 2.4448x; 1.0374x over previous
#include <cuda_runtime.h>
#include <cstdint>

#define N_NODES 100000
#define N_EDGES 320000
#define N_GRAPHS 4096
#define HID 256
#define NFEAT 28

// ---------------- device scratch (zero-fill bss, no runtime alloc) ----------
__device__ float d_agg28[N_NODES * NFEAT];
__device__ float d_agg[N_NODES * HID];
__device__ float d_x1[N_NODES * HID];
__device__ float d_x2[N_NODES * HID];
__device__ float d_x3[N_NODES * HID];
__device__ float d_x4[N_NODES * HID];
__device__ float d_g[N_GRAPHS * 4 * HID];
__device__ float d_h1[N_GRAPHS * HID];
__device__ float d_h2[N_GRAPHS * HID];
__device__ float d_h3[N_GRAPHS * HID];

// ---------------- utility kernels -------------------------------------------
__global__ void zero_f4(float4* p, int n4) {
    int i = blockIdx.x * blockDim.x + threadIdx.x;
    if (i < n4) p[i] = make_float4(0.f, 0.f, 0.f, 0.f);
}

__device__ __forceinline__ void red_add_v4(float* p, float4 v) {
    asm volatile("red.global.add.v4.f32 [%0], {%1,%2,%3,%4};"
                 :: "l"(p), "f"(v.x), "f"(v.y), "f"(v.z), "f"(v.w)
                 : "memory");
}

// scatter-add x[src] (28 feats = 7 float4) into agg28[dst]; 8 threads/edge
__global__ void scatter28(const float* __restrict__ x,
                          const int* __restrict__ ei,
                          float* __restrict__ agg, int E) {
    int t = blockIdx.x * blockDim.x + threadIdx.x;
    int e = t >> 3;
    int c = t & 7;
    if (e >= E || c >= 7) return;
    int s = ei[e];
    int d = ei[E + e];
    float4 v = *(const float4*)(x + (size_t)s * NFEAT + c * 4);
    red_add_v4(agg + (size_t)d * NFEAT + c * 4, v);
}

// scatter-add x[src] (256 feats) into agg[dst]; 64 threads/edge, red.v4
__global__ void scatter256(const float* __restrict__ x,
                           const int* __restrict__ ei,
                           float* __restrict__ agg, int E) {
    int t = blockIdx.x * blockDim.x + threadIdx.x;
    int e = t >> 6;
    int c = (t & 63) << 2;
    if (e >= E) return;
    int s = ei[e];
    int d = ei[E + e];
    float4 v = *(const float4*)(x + (size_t)s * HID + c);
    red_add_v4(agg + (size_t)d * HID + c, v);
}

// layer 1: out = relu(agg28 @ W_rel^T + b + x @ W_root^T)  (K=28, NOUT=256)
__global__ __launch_bounds__(256)
void layer1_kernel(const float* __restrict__ agg28, const float* __restrict__ x,
                   const float* __restrict__ W_rel, const float* __restrict__ b,
                   const float* __restrict__ W_root, float* __restrict__ out, int M) {
    __shared__ float sa[16][NFEAT];
    __shared__ float sx[16][NFEAT];
    int r0 = blockIdx.x * 16;
    for (int i = threadIdx.x; i < 16 * NFEAT; i += 256) {
        int r = i / NFEAT, c = i % NFEAT;
        int row = r0 + r;
        sa[r][c] = (row < M) ? agg28[(size_t)row * NFEAT + c] : 0.f;
        sx[r][c] = (row < M) ? x[(size_t)row * NFEAT + c] : 0.f;
    }
    __syncthreads();
    int o = threadIdx.x;  // output column 0..255
    float wr[NFEAT], wo[NFEAT];
#pragma unroll
    for (int k = 0; k < NFEAT; k++) {
        wr[k] = W_rel[o * NFEAT + k];
        wo[k] = W_root[o * NFEAT + k];
    }
    float bo = b[o];
#pragma unroll 4
    for (int r = 0; r < 16; r++) {
        int row = r0 + r;
        if (row >= M) break;
        float acc = bo;
#pragma unroll
        for (int k = 0; k < NFEAT; k++) acc += sa[r][k] * wr[k] + sx[r][k] * wo[k];
        out[(size_t)row * HID + o] = fmaxf(acc, 0.f);
    }
}

// =================== tf32 tensor-core dual-segment NT GEMM ===================
// C[M,256] = relu?( bias + A0[M,K0] @ B0[256,K0]^T + A1[M,K1] @ B1[256,K1]^T )
// 128x128 CTA tile, BK=16, 3-stage cp.async pipeline, 8 warps (4M x 2N),
// warp tile 32x64, mma.sync.m16n8k8 tf32 with cvt.rna at fragment load.

#define GBM 128
#define GBN 128
#define GBK 16
#define SSTR 20     // smem row stride in floats
#define STAGES 3
#define STAGE_F ((GBM + GBN) * SSTR)              // floats per stage
#define GEMM_SMEM_BYTES (STAGES * STAGE_F * 4)    // 61440

__device__ __forceinline__ uint32_t f2tf32(float x) {
    uint32_t u;
    asm("cvt.rna.tf32.f32 %0, %1;" : "=r"(u) : "f"(x));
    return u;
}

__device__ __forceinline__ void cp_async16(uint32_t dst, const void* src, int nbytes) {
    asm volatile("cp.async.cg.shared.global [%0], [%1], 16, %2;"
                 :: "r"(dst), "l"(src), "r"(nbytes) : "memory");
}

__device__ __forceinline__ void mma_tf32(float* c, const uint32_t* a, const uint32_t* b) {
    asm volatile(
        "mma.sync.aligned.m16n8k8.row.col.f32.tf32.tf32.f32 "
        "{%0,%1,%2,%3}, {%4,%5,%6,%7}, {%8,%9}, {%0,%1,%2,%3};"
        : "+f"(c[0]), "+f"(c[1]), "+f"(c[2]), "+f"(c[3])
        : "r"(a[0]), "r"(a[1]), "r"(a[2]), "r"(a[3]), "r"(b[0]), "r"(b[1]));
}

__global__ __launch_bounds__(256, 2)
void gemm_tf32_dual(const float* __restrict__ A0, int lda0,
                    const float* __restrict__ B0, int ldb0, int K0,
                    const float* __restrict__ A1, int lda1,
                    const float* __restrict__ B1, int ldb1, int K1,
                    const float* __restrict__ bias, float* __restrict__ C,
                    int M, int ldc, int relu) {
    extern __shared__ float smem[];
    float* Asm = smem;                         // [STAGES][GBM*SSTR]
    float* Bsm = smem + STAGES * GBM * SSTR;   // [STAGES][GBN*SSTR]
    uint32_t As_base = (uint32_t)__cvta_generic_to_shared(Asm);
    uint32_t Bs_base = (uint32_t)__cvta_generic_to_shared(Bsm);

    int tid = threadIdx.x;
    int lane = tid & 31;
    int wid = tid >> 5;
    int wm = wid & 3;   // 0..3 -> 32-row slice
    int wn = wid >> 2;  // 0..1 -> 64-col slice
    int bm = blockIdx.y * GBM;
    int bn = blockIdx.x * GBN;

    float acc[2][8][4];
#pragma unroll
    for (int mt = 0; mt < 2; mt++)
#pragma unroll
        for (int nt = 0; nt < 8; nt++)
#pragma unroll
            for (int i = 0; i < 4; i++) acc[mt][nt][i] = 0.f;

    int nk0 = K0 / GBK;
    int nk = nk0 + K1 / GBK;

    // copy mapping: 256 threads cover 128 rows x 16 cols (64B/row) in 2 passes
    int lr = tid >> 2;            // 0..63
    int lc = (tid & 3) << 2;      // 0,4,8,12

    // issue cp.async for pipeline stage s into buffer buf
    auto issue_stage = [&](int s, int bufi) {
        const float* A; const float* B; int lda, ldb, ko;
        if (s < nk0) { A = A0; B = B0; lda = lda0; ldb = ldb0; ko = s * GBK; }
        else         { A = A1; B = B1; lda = lda1; ldb = ldb1; ko = (s - nk0) * GBK; }
#pragma unroll
        for (int j = 0; j < 2; j++) {
            int rr = lr + j * 64;
            int row = bm + rr;
            int okA = (row < M);
            const float* gA = A + (size_t)(okA ? row : 0) * lda + ko + lc;
            uint32_t da = As_base + (uint32_t)(bufi * (GBM * SSTR) + rr * SSTR + lc) * 4u;
            cp_async16(da, gA, okA ? 16 : 0);
            const float* gB = B + (size_t)(bn + rr) * ldb + ko + lc;
            uint32_t db = Bs_base + (uint32_t)(bufi * (GBN * SSTR) + rr * SSTR + lc) * 4u;
            cp_async16(db, gB, 16);
        }
        asm volatile("cp.async.commit_group;" ::: "memory");
    };

    // prologue: prefetch STAGES-1 stages
#pragma unroll
    for (int s = 0; s < STAGES - 1; s++) {
        if (s < nk) issue_stage(s, s);
        else asm volatile("cp.async.commit_group;" ::: "memory");
    }

    int grp = lane >> 2;  // 0..7
    int qid = lane & 3;   // 0..3
    int buf = 0;

    for (int it = 0; it < nk; ++it) {
        asm volatile("cp.async.wait_group %0;" :: "n"(STAGES - 2));
        __syncthreads();

        // prefetch stage it+STAGES-1 into the buffer consumed at it-1
        int nx = it + STAGES - 1;
        if (nx < nk) issue_stage(nx, (buf + STAGES - 1) % STAGES);
        else asm volatile("cp.async.commit_group;" ::: "memory");

        const float* Ab = Asm + buf * (GBM * SSTR);
        const float* Bb = Bsm + buf * (GBN * SSTR);
#pragma unroll
        for (int kk = 0; kk < GBK; kk += 8) {
            uint32_t af[2][4];
            uint32_t bfr[8][2];
#pragma unroll
            for (int mt = 0; mt < 2; mt++) {
                int r0 = wm * 32 + mt * 16 + grp;
                af[mt][0] = f2tf32(Ab[(r0    ) * SSTR + kk + qid]);
                af[mt][1] = f2tf32(Ab[(r0 + 8) * SSTR + kk + qid]);
                af[mt][2] = f2tf32(Ab[(r0    ) * SSTR + kk + qid + 4]);
                af[mt][3] = f2tf32(Ab[(r0 + 8) * SSTR + kk + qid + 4]);
            }
#pragma unroll
            for (int nt = 0; nt < 8; nt++) {
                int n0 = wn * 64 + nt * 8 + grp;
                bfr[nt][0] = f2tf32(Bb[n0 * SSTR + kk + qid]);
                bfr[nt][1] = f2tf32(Bb[n0 * SSTR + kk + qid + 4]);
            }
#pragma unroll
            for (int mt = 0; mt < 2; mt++)
#pragma unroll
                for (int nt = 0; nt < 8; nt++) mma_tf32(acc[mt][nt], af[mt], bfr[nt]);
        }
        buf = (buf + 1) % STAGES;
    }

    // ---- epilogue: bias + optional relu ----
#pragma unroll
    for (int mt = 0; mt < 2; mt++) {
#pragma unroll
        for (int nt = 0; nt < 8; nt++) {
            int row = bm + wm * 32 + mt * 16 + grp;
            int col = bn + wn * 64 + nt * 8 + 2 * qid;
            float b0 = bias[col], b1 = bias[col + 1];
            float2 v0, v1;
            v0.x = acc[mt][nt][0] + b0; v0.y = acc[mt][nt][1] + b1;
            v1.x = acc[mt][nt][2] + b0; v1.y = acc[mt][nt][3] + b1;
            if (relu) {
                v0.x = fmaxf(v0.x, 0.f); v0.y = fmaxf(v0.y, 0.f);
                v1.x = fmaxf(v1.x, 0.f); v1.y = fmaxf(v1.y, 0.f);
            }
            if (row < M)     *(float2*)(C + (size_t)row * ldc + col) = v0;
            if (row + 8 < M) *(float2*)(C + (size_t)(row + 8) * ldc + col) = v1;
        }
    }
}

// ------------- pooling: per-graph mean over concat(x1..x4) -------------------
__device__ __forceinline__ int lower_bound_i(const int* a, int n, int v) {
    int lo = 0, hi = n;
    while (lo < hi) {
        int mid = (lo + hi) >> 1;
        if (a[mid] < v) lo = mid + 1;
        else hi = mid;
    }
    return lo;
}

__global__ __launch_bounds__(256)
void pool_kernel(const float* __restrict__ x1, const float* __restrict__ x2,
                 const float* __restrict__ x3, const float* __restrict__ x4,
                 const int* __restrict__ batch, float* __restrict__ g, int N) {
    int gr = blockIdx.x;
    __shared__ int s_range[2];
    if (threadIdx.x == 0) {
        s_range[0] = lower_bound_i(batch, N, gr);
        s_range[1] = lower_bound_i(batch, N, gr + 1);
    }
    __syncthreads();
    int start = s_range[0], end = s_range[1];
    int tid = threadIdx.x;  // column 0..255
    float a0 = 0.f, a1 = 0.f, a2 = 0.f, a3 = 0.f;
    for (int n = start; n < end; n++) {
        size_t off = (size_t)n * HID + tid;
        a0 += x1[off];
        a1 += x2[off];
        a2 += x3[off];
        a3 += x4[off];
    }
    float inv = 1.f / fmaxf((float)(end - start), 1.f);
    size_t go = (size_t)gr * (4 * HID);
    g[go + 0 * HID + tid] = a0 * inv;
    g[go + 1 * HID + tid] = a1 * inv;
    g[go + 2 * HID + tid] = a2 * inv;
    g[go + 3 * HID + tid] = a3 * inv;
}

// ------------- final fc4: [G,256] @ w[256] + b -> [G] ------------------------
__global__ void fc4_kernel(const float* __restrict__ h, const float* __restrict__ w,
                           const float* __restrict__ b, float* __restrict__ out, int G) {
    int t = blockIdx.x * blockDim.x + threadIdx.x;
    int warp = t >> 5;
    int lane = t & 31;
    if (warp >= G) return;
    float acc = 0.f;
#pragma unroll
    for (int c = lane; c < HID; c += 32) acc += h[(size_t)warp * HID + c] * w[c];
#pragma unroll
    for (int off = 16; off; off >>= 1) acc += __shfl_xor_sync(0xFFFFFFFFu, acc, off);
    if (lane == 0) out[warp] = acc + b[0];
}

// ---------------- host orchestration ----------------------------------------
extern "C" void kernel_launch(void* const* d_in, const int* in_sizes, int n_in,
                              void* d_out, int out_size) {
    const float* x = (const float*)d_in[0];
    const int* ei = (const int*)d_in[1];       // int32 (JAX x64 disabled)
    const int* batch = (const int*)d_in[2];    // int32
    const float* W_rel[4] = {(const float*)d_in[3], (const float*)d_in[6],
                             (const float*)d_in[9], (const float*)d_in[12]};
    const float* b_rel[4] = {(const float*)d_in[4], (const float*)d_in[7],
                             (const float*)d_in[10], (const float*)d_in[13]};
    const float* W_root[4] = {(const float*)d_in[5], (const float*)d_in[8],
                              (const float*)d_in[11], (const float*)d_in[14]};
    const float* fc1_w = (const float*)d_in[15];
    const float* fc1_b = (const float*)d_in[16];
    const float* fc2_w = (const float*)d_in[17];
    const float* fc2_b = (const float*)d_in[18];
    const float* fc3_w = (const float*)d_in[19];
    const float* fc3_b = (const float*)d_in[20];
    const float* fc4_w = (const float*)d_in[21];
    const float* fc4_b = (const float*)d_in[22];
    float* out = (float*)d_out;

    int N = in_sizes[0] / NFEAT;   // 100000
    int E = in_sizes[1] / 2;       // 320000
    int G = out_size;              // 4096

    static float *agg28 = 0, *agg = 0, *x1 = 0, *x2 = 0, *x3 = 0, *x4 = 0,
                 *g = 0, *h1 = 0, *h2 = 0, *h3 = 0;
    if (!agg28) {
        cudaGetSymbolAddress((void**)&agg28, d_agg28);
        cudaGetSymbolAddress((void**)&agg, d_agg);
        cudaGetSymbolAddress((void**)&x1, d_x1);
        cudaGetSymbolAddress((void**)&x2, d_x2);
        cudaGetSymbolAddress((void**)&x3, d_x3);
        cudaGetSymbolAddress((void**)&x4, d_x4);
        cudaGetSymbolAddress((void**)&g, d_g);
        cudaGetSymbolAddress((void**)&h1, d_h1);
        cudaGetSymbolAddress((void**)&h2, d_h2);
        cudaGetSymbolAddress((void**)&h3, d_h3);
        cudaFuncSetAttribute(gemm_tf32_dual,
                             cudaFuncAttributeMaxDynamicSharedMemorySize,
                             GEMM_SMEM_BYTES);
    }

    float* xs[4] = {x1, x2, x3, x4};

    // ---- layer 1: scatter in 28-dim space, then tiny-K fused GEMM (fp32) ----
    {
        int n4 = N * NFEAT / 4;
        zero_f4<<<(n4 + 255) / 256, 256>>>((float4*)agg28, n4);
        int tot = E * 8;
        scatter28<<<(tot + 255) / 256, 256>>>(x, ei, agg28, E);
        layer1_kernel<<<(N + 15) / 16, 256>>>(agg28, x, W_rel[0], b_rel[0], W_root[0], x1, N);
    }

    // ---- layers 2..4 : scatter (red.v4) + tf32 dual GEMM (cp.async) ----
    for (int l = 1; l < 4; l++) {
        const float* xin = xs[l - 1];
        float* xout = xs[l];
        int n4 = N * HID / 4;
        zero_f4<<<(n4 + 255) / 256, 256>>>((float4*)agg, n4);
        int tot = E * 64;
        scatter256<<<(tot + 255) / 256, 256>>>(xin, ei, agg, E);
        dim3 grid(HID / GBN, (N + GBM - 1) / GBM);
        gemm_tf32_dual<<<grid, 256, GEMM_SMEM_BYTES>>>(
            agg, HID, W_rel[l], HID, HID,
            xin, HID, W_root[l], HID, HID,
            b_rel[l], xout, N, HID, 1);
    }

    // ---- global mean pool ----
    pool_kernel<<<G, 256>>>(x1, x2, x3, x4, batch, g, N);

    // ---- MLP (tf32 for fc1..fc3, warp-reduce for fc4) ----
    {
        dim3 grid(HID / GBN, (G + GBM - 1) / GBM);
        gemm_tf32_dual<<<grid, 256, GEMM_SMEM_BYTES>>>(
            g, 4 * HID, fc1_w, 4 * HID, 4 * HID,
            (const float*)0, 0, (const float*)0, 0, 0,
            fc1_b, h1, G, HID, 1);
        gemm_tf32_dual<<<grid, 256, GEMM_SMEM_BYTES>>>(
            h1, HID, fc2_w, HID, HID,
            (const float*)0, 0, (const float*)0, 0, 0,
            fc2_b, h2, G, HID, 1);
        gemm_tf32_dual<<<grid, 256, GEMM_SMEM_BYTES>>>(
            h2, HID, fc3_w, HID, HID,
            (const float*)0, 0, (const float*)0, 0, 0,
            fc3_b, h3, G, HID, 1);
        int tot = G * 32;
        fc4_kernel<<<(tot + 255) / 256, 256>>>(h3, fc4_w, fc4_b, out, G);
    }
}